// round 1
// baseline (speedup 1.0000x reference)
#include <cuda_runtime.h>
#include <cuda_bf16.h>

#define BATCH 256
#define NPOS 4
#define NNEG 1024
#define DIM 512
#define CHUNKS 4
#define ROWS_PER_CHUNK (NNEG / CHUNKS)   // 256
#define WARPS_B 8
#define EPS_F 1e-8f
#define INV_T 10.0f

// Scratch (no device allocation allowed) — rewritten every launch, no zeroing needed.
__device__ float g_pos_sim[BATCH * NPOS];
__device__ float g_norm_a[BATCH];
__device__ float g_exp_part[BATCH * CHUNKS * WARPS_B];
__device__ int   g_cnt_part[BATCH * CHUNKS * WARPS_B * NPOS];

// ---------------------------------------------------------------------------
// Kernel A: per-b anchor norm + pos_sim[b][p].  grid=BATCH, block=128 (4 warps,
// warp w handles positive p=w; all warps redundantly compute ||a||).
// ---------------------------------------------------------------------------
__global__ void rrl_prep_kernel(const float* __restrict__ anchor,
                                const float* __restrict__ positives) {
    const int b    = blockIdx.x;
    const int w    = threadIdx.x >> 5;
    const int lane = threadIdx.x & 31;

    const float4* a4 = reinterpret_cast<const float4*>(anchor + (size_t)b * DIM);
    const float4* p4 = reinterpret_cast<const float4*>(positives + ((size_t)b * NPOS + w) * DIM);

    float dot = 0.f, sqa = 0.f, sqp = 0.f;
#pragma unroll
    for (int k = 0; k < 4; k++) {
        float4 av = a4[lane + 32 * k];
        float4 pv = p4[lane + 32 * k];
        dot += av.x * pv.x + av.y * pv.y + av.z * pv.z + av.w * pv.w;
        sqa += av.x * av.x + av.y * av.y + av.z * av.z + av.w * av.w;
        sqp += pv.x * pv.x + pv.y * pv.y + pv.z * pv.z + pv.w * pv.w;
    }
#pragma unroll
    for (int o = 16; o; o >>= 1) {
        dot += __shfl_xor_sync(0xffffffffu, dot, o);
        sqa += __shfl_xor_sync(0xffffffffu, sqa, o);
        sqp += __shfl_xor_sync(0xffffffffu, sqp, o);
    }
    if (lane == 0) {
        float na = sqrtf(sqa);
        float np = sqrtf(sqp);
        g_pos_sim[b * NPOS + w] = dot / fmaxf(na * np, EPS_F);
        if (w == 0) g_norm_a[b] = na;
    }
}

// ---------------------------------------------------------------------------
// Kernel B: streaming pass over negatives.  grid = BATCH*CHUNKS, block = 256.
// Block (b, chunk): 8 warps, each warp processes 32 rows (one row = 512 floats,
// 4x float4 per lane, coalesced).  Fused dot + sumsq; accumulate sum of
// exp(sim/T) and 4 strict-greater counters.  Per-warp partials to scratch.
// ---------------------------------------------------------------------------
__global__ void __launch_bounds__(256) rrl_neg_kernel(const float* __restrict__ anchor,
                                                      const float* __restrict__ negatives) {
    const int b     = blockIdx.x >> 2;
    const int chunk = blockIdx.x & 3;
    const int w     = threadIdx.x >> 5;
    const int lane  = threadIdx.x & 31;

    const float4* a4 = reinterpret_cast<const float4*>(anchor + (size_t)b * DIM);
    float4 af[4];
#pragma unroll
    for (int k = 0; k < 4; k++) af[k] = a4[lane + 32 * k];

    const float norm_a = g_norm_a[b];
    const float t0 = g_pos_sim[b * NPOS + 0];
    const float t1 = g_pos_sim[b * NPOS + 1];
    const float t2 = g_pos_sim[b * NPOS + 2];
    const float t3 = g_pos_sim[b * NPOS + 3];

    float sum_exp = 0.f;
    int c0 = 0, c1 = 0, c2 = 0, c3 = 0;

    const int row_base = chunk * ROWS_PER_CHUNK + w;
#pragma unroll 2
    for (int i = 0; i < ROWS_PER_CHUNK / WARPS_B; i++) {
        const int row = row_base + i * WARPS_B;
        const float4* n4 =
            reinterpret_cast<const float4*>(negatives + ((size_t)b * NNEG + row) * DIM);
        float dot = 0.f, sq = 0.f;
#pragma unroll
        for (int k = 0; k < 4; k++) {
            float4 v = n4[lane + 32 * k];
            dot += af[k].x * v.x + af[k].y * v.y + af[k].z * v.z + af[k].w * v.w;
            sq  += v.x * v.x + v.y * v.y + v.z * v.z + v.w * v.w;
        }
#pragma unroll
        for (int o = 16; o; o >>= 1) {
            dot += __shfl_xor_sync(0xffffffffu, dot, o);
            sq  += __shfl_xor_sync(0xffffffffu, sq, o);
        }
        // every lane holds the full reduction; accumulate uniformly (no divergence)
        const float sim = dot / fmaxf(norm_a * sqrtf(sq), EPS_F);
        sum_exp += expf(sim * INV_T);
        c0 += (sim > t0);
        c1 += (sim > t1);
        c2 += (sim > t2);
        c3 += (sim > t3);
    }

    if (lane == 0) {
        const int idx = (b * CHUNKS + chunk) * WARPS_B + w;
        g_exp_part[idx] = sum_exp;
        g_cnt_part[idx * NPOS + 0] = c0;
        g_cnt_part[idx * NPOS + 1] = c1;
        g_cnt_part[idx * NPOS + 2] = c2;
        g_cnt_part[idx * NPOS + 3] = c3;
    }
}

// ---------------------------------------------------------------------------
// Kernel C: final reduction.  1 block, 256 threads, thread = batch index b.
// ---------------------------------------------------------------------------
__global__ void rrl_final_kernel(float* __restrict__ out) {
    const int b = threadIdx.x;

    float se = 0.f;
    int cnt[NPOS] = {0, 0, 0, 0};
#pragma unroll 4
    for (int j = 0; j < CHUNKS * WARPS_B; j++) {
        const int idx = b * (CHUNKS * WARPS_B) + j;
        se += g_exp_part[idx];
#pragma unroll
        for (int p = 0; p < NPOS; p++) cnt[p] += g_cnt_part[idx * NPOS + p];
    }

    float ps[NPOS], ep[NPOS];
    float denom = se;
#pragma unroll
    for (int p = 0; p < NPOS; p++) {
        ps[p] = g_pos_sim[b * NPOS + p];
        ep[p] = expf(ps[p] * INV_T);
        denom += ep[p];
    }

    float err = 0.f, psum = 0.f;
#pragma unroll
    for (int p = 0; p < NPOS; p++) {
        int rank = cnt[p];
#pragma unroll
        for (int q = 0; q < NPOS; q++) {
            if (ps[q] > ps[p]) rank++;
            else if (q < p && ps[q] == ps[p]) rank++;
        }
        err  += (ep[p] / denom) / (float)(rank + 1);
        psum += ps[p];
    }

    __shared__ float s_err[256];
    __shared__ float s_pos[256];
    s_err[b] = err;
    s_pos[b] = psum;
    __syncthreads();
    for (int off = 128; off; off >>= 1) {
        if (b < off) {
            s_err[b] += s_err[b + off];
            s_pos[b] += s_pos[b + off];
        }
        __syncthreads();
    }
    if (b == 0) {
        const float loss = -s_err[0] / (float)BATCH +
                           0.3f * (1.0f - s_pos[0] / (float)(BATCH * NPOS));
        out[0] = loss;
    }
}

// ---------------------------------------------------------------------------
extern "C" void kernel_launch(void* const* d_in, const int* in_sizes, int n_in,
                              void* d_out, int out_size) {
    const float* anchor    = (const float*)d_in[0];
    const float* positives = (const float*)d_in[1];
    const float* negatives = (const float*)d_in[2];
    float* out = (float*)d_out;

    rrl_prep_kernel<<<BATCH, 128>>>(anchor, positives);
    rrl_neg_kernel<<<BATCH * CHUNKS, 256>>>(anchor, negatives);
    rrl_final_kernel<<<1, 256>>>(out);
}

// round 3
// speedup vs baseline: 1.2464x; 1.2464x over previous
#include <cuda_runtime.h>
#include <cuda_bf16.h>

#define BATCH 256
#define NPOS 4
#define NNEG 1024
#define DIM 512
#define CHUNKS 4
#define ROWS_PER_CHUNK (NNEG / CHUNKS)        // 256
#define WARPS_B 8
#define ROWS_PER_WARP (ROWS_PER_CHUNK / WARPS_B)  // 32
#define RBATCH 4
#define EPS_F 1e-8f
#define INV_T 10.0f

// Scratch (device allocation forbidden) — fully rewritten each launch.
__device__ float g_pos_sim[BATCH * NPOS];
__device__ float g_exp_part[BATCH * CHUNKS];
__device__ int4  g_cnt_part[BATCH * CHUNKS];

// ---------------------------------------------------------------------------
// Kernel B: one block per (b, chunk).  Prologue: warps 0-3 compute pos_sim and
// anchor norm (fused former prep kernel).  Main loop: each warp streams 32
// negative rows in batches of 4 (16 LDG.128 in flight), interleaved butterfly
// reductions, cheap MUFU tail (rsqrt + __expf).  Epilogue: block-level
// reduction -> one partial per block.
// ---------------------------------------------------------------------------
__global__ void __launch_bounds__(256) rrl_neg_kernel(const float* __restrict__ anchor,
                                                      const float* __restrict__ positives,
                                                      const float* __restrict__ negatives) {
    const int b     = blockIdx.x >> 2;
    const int chunk = blockIdx.x & 3;
    const int w     = threadIdx.x >> 5;
    const int lane  = threadIdx.x & 31;

    __shared__ float s_pos[NPOS];
    __shared__ float s_rinv;
    __shared__ float s_exp[WARPS_B];
    __shared__ int   s_cnt[WARPS_B][NPOS];

    // ---- anchor fragment (kept in registers for the whole kernel) ----
    const float4* a4 = reinterpret_cast<const float4*>(anchor + (size_t)b * DIM);
    float4 af[4];
#pragma unroll
    for (int k = 0; k < 4; k++) af[k] = a4[lane + 32 * k];

    // ---- prologue: pos_sim + anchor norm (warps 0-3) ----
    if (w < NPOS) {
        const float4* p4 =
            reinterpret_cast<const float4*>(positives + ((size_t)b * NPOS + w) * DIM);
        float dot = 0.f, sqa = 0.f, sqp = 0.f;
#pragma unroll
        for (int k = 0; k < 4; k++) {
            float4 pv = p4[lane + 32 * k];
            dot += af[k].x * pv.x + af[k].y * pv.y + af[k].z * pv.z + af[k].w * pv.w;
            sqa += af[k].x * af[k].x + af[k].y * af[k].y + af[k].z * af[k].z + af[k].w * af[k].w;
            sqp += pv.x * pv.x + pv.y * pv.y + pv.z * pv.z + pv.w * pv.w;
        }
#pragma unroll
        for (int o = 16; o; o >>= 1) {
            dot += __shfl_xor_sync(0xffffffffu, dot, o);
            sqa += __shfl_xor_sync(0xffffffffu, sqa, o);
            sqp += __shfl_xor_sync(0xffffffffu, sqp, o);
        }
        if (lane == 0) {
            const float na = sqrtf(sqa);
            const float sim = dot / fmaxf(na * sqrtf(sqp), EPS_F);
            s_pos[w] = sim;
            if (w == 0) s_rinv = 1.0f / na;
            if (chunk == 0) g_pos_sim[b * NPOS + w] = sim;
        }
    }
    __syncthreads();

    const float rinv_a = s_rinv;
    const float t0 = s_pos[0], t1 = s_pos[1], t2 = s_pos[2], t3 = s_pos[3];

    float sum_exp = 0.f;
    int c0 = 0, c1 = 0, c2 = 0, c3 = 0;

    // warp w owns rows [w*32, w*32+32) of this chunk
    const float* neg_base =
        negatives + ((size_t)b * NNEG + chunk * ROWS_PER_CHUNK + w * ROWS_PER_WARP) * DIM;

    for (int i = 0; i < ROWS_PER_WARP; i += RBATCH) {
        float4 v[RBATCH][4];
#pragma unroll
        for (int r = 0; r < RBATCH; r++) {
            const float4* n4 =
                reinterpret_cast<const float4*>(neg_base + (size_t)(i + r) * DIM);
#pragma unroll
            for (int k = 0; k < 4; k++) v[r][k] = n4[lane + 32 * k];
        }

        float dot[RBATCH], sq[RBATCH];
#pragma unroll
        for (int r = 0; r < RBATCH; r++) {
            float d = 0.f, s = 0.f;
#pragma unroll
            for (int k = 0; k < 4; k++) {
                d += af[k].x * v[r][k].x + af[k].y * v[r][k].y +
                     af[k].z * v[r][k].z + af[k].w * v[r][k].w;
                s += v[r][k].x * v[r][k].x + v[r][k].y * v[r][k].y +
                     v[r][k].z * v[r][k].z + v[r][k].w * v[r][k].w;
            }
            dot[r] = d;
            sq[r]  = s;
        }

        // interleaved butterfly reductions: 8 independent chains per level
#pragma unroll
        for (int o = 16; o; o >>= 1) {
#pragma unroll
            for (int r = 0; r < RBATCH; r++) {
                dot[r] += __shfl_xor_sync(0xffffffffu, dot[r], o);
                sq[r]  += __shfl_xor_sync(0xffffffffu, sq[r], o);
            }
        }

#pragma unroll
        for (int r = 0; r < RBATCH; r++) {
            const float sim = dot[r] * (rinv_a * rsqrtf(fmaxf(sq[r], EPS_F * EPS_F)));
            sum_exp += __expf(sim * INV_T);
            c0 += (sim > t0);
            c1 += (sim > t1);
            c2 += (sim > t2);
            c3 += (sim > t3);
        }
    }

    // ---- block reduction of partials ----
    if (lane == 0) {
        s_exp[w]    = sum_exp;
        s_cnt[w][0] = c0; s_cnt[w][1] = c1; s_cnt[w][2] = c2; s_cnt[w][3] = c3;
    }
    __syncthreads();
    if (threadIdx.x == 0) {
        float se = 0.f;
        int k0 = 0, k1 = 0, k2 = 0, k3 = 0;
#pragma unroll
        for (int j = 0; j < WARPS_B; j++) {
            se += s_exp[j];
            k0 += s_cnt[j][0]; k1 += s_cnt[j][1]; k2 += s_cnt[j][2]; k3 += s_cnt[j][3];
        }
        g_exp_part[blockIdx.x] = se;
        g_cnt_part[blockIdx.x] = make_int4(k0, k1, k2, k3);
    }
}

// ---------------------------------------------------------------------------
// Kernel C: final reduction.  1 block, 256 threads, thread b folds 4 chunk
// partials, computes ranks/softmax/expected RR, block-reduces to the scalar.
// ---------------------------------------------------------------------------
__global__ void rrl_final_kernel(float* __restrict__ out) {
    const int b = threadIdx.x;

    float se = 0.f;
    int cnt[NPOS] = {0, 0, 0, 0};
#pragma unroll
    for (int c = 0; c < CHUNKS; c++) {
        const int idx = b * CHUNKS + c;
        se += g_exp_part[idx];
        const int4 k = g_cnt_part[idx];
        cnt[0] += k.x; cnt[1] += k.y; cnt[2] += k.z; cnt[3] += k.w;
    }

    float ps[NPOS], ep[NPOS];
    float denom = se;
#pragma unroll
    for (int p = 0; p < NPOS; p++) {
        ps[p] = g_pos_sim[b * NPOS + p];
        ep[p] = expf(ps[p] * INV_T);
        denom += ep[p];
    }

    float err = 0.f, psum = 0.f;
#pragma unroll
    for (int p = 0; p < NPOS; p++) {
        int rank = cnt[p];
#pragma unroll
        for (int q = 0; q < NPOS; q++) {
            if (ps[q] > ps[p]) rank++;
            else if (q < p && ps[q] == ps[p]) rank++;
        }
        err  += (ep[p] / denom) / (float)(rank + 1);
        psum += ps[p];
    }

    __shared__ float s_err[256];
    __shared__ float s_pos[256];
    s_err[b] = err;
    s_pos[b] = psum;
    __syncthreads();
    for (int off = 128; off; off >>= 1) {
        if (b < off) {
            s_err[b] += s_err[b + off];
            s_pos[b] += s_pos[b + off];
        }
        __syncthreads();
    }
    if (b == 0) {
        out[0] = -s_err[0] / (float)BATCH +
                 0.3f * (1.0f - s_pos[0] / (float)(BATCH * NPOS));
    }
}

// ---------------------------------------------------------------------------
extern "C" void kernel_launch(void* const* d_in, const int* in_sizes, int n_in,
                              void* d_out, int out_size) {
    const float* anchor    = (const float*)d_in[0];
    const float* positives = (const float*)d_in[1];
    const float* negatives = (const float*)d_in[2];

    rrl_neg_kernel<<<BATCH * CHUNKS, 256>>>(anchor, positives, negatives);
    rrl_final_kernel<<<1, 256>>>((float*)d_out);
}

// round 4
// speedup vs baseline: 1.4215x; 1.1405x over previous
#include <cuda_runtime.h>
#include <cuda_bf16.h>

#define BATCH 256
#define NPOS 4
#define NNEG 1024
#define DIM 512
#define CHUNKS 4
#define ROWS_PER_CHUNK (NNEG / CHUNKS)            // 256
#define WARPS_B 8
#define ROWS_PER_WARP (ROWS_PER_CHUNK / WARPS_B)  // 32
#define RBATCH 4
#define NBLOCKS (BATCH * CHUNKS)                  // 1024
#define EPS_F 1e-8f
#define INV_T 10.0f

// Scratch (device allocation forbidden) — fully rewritten each launch.
__device__ float g_pos_sim[BATCH * NPOS];
__device__ float g_exp_part[NBLOCKS];
__device__ int4  g_cnt_part[NBLOCKS];
__device__ unsigned int g_ticket = 0;   // reset by the finalizing block each launch

__device__ __forceinline__ float4 ldcs4(const float4* p) {
    return __ldcs(p);
}

// ---------------------------------------------------------------------------
// Single fused kernel.  One block per (b, chunk).
//   Prologue : warps 0-3 compute pos_sim[b][*] + 1/||a||  (redundant per chunk).
//   Main loop: each warp streams 32 negative rows, 4 at a time, software-
//              pipelined: per-lane FMA consumption -> issue next 16 LDG.128 ->
//              shuffle tree + MUFU tail of previous batch.
//   Epilogue : block partial -> global; last block (atomic ticket) folds all
//              partials deterministically and writes the scalar loss.
// ---------------------------------------------------------------------------
__global__ void __launch_bounds__(256) rrl_fused_kernel(const float* __restrict__ anchor,
                                                        const float* __restrict__ positives,
                                                        const float* __restrict__ negatives,
                                                        float* __restrict__ out) {
    const int b     = blockIdx.x >> 2;
    const int chunk = blockIdx.x & 3;
    const int w     = threadIdx.x >> 5;
    const int lane  = threadIdx.x & 31;

    __shared__ float s_pos[NPOS];
    __shared__ float s_rinv;
    __shared__ float s_exp[WARPS_B];
    __shared__ int   s_cnt[WARPS_B][NPOS];
    __shared__ int   s_last;

    // ---- anchor fragment (register-resident for the whole kernel) ----
    const float4* a4 = reinterpret_cast<const float4*>(anchor + (size_t)b * DIM);
    float4 af[4];
#pragma unroll
    for (int k = 0; k < 4; k++) af[k] = a4[lane + 32 * k];

    // ---- prologue: pos_sim + anchor norm (warps 0-3) ----
    if (w < NPOS) {
        const float4* p4 =
            reinterpret_cast<const float4*>(positives + ((size_t)b * NPOS + w) * DIM);
        float dot = 0.f, sqa = 0.f, sqp = 0.f;
#pragma unroll
        for (int k = 0; k < 4; k++) {
            float4 pv = p4[lane + 32 * k];
            dot += af[k].x * pv.x + af[k].y * pv.y + af[k].z * pv.z + af[k].w * pv.w;
            sqa += af[k].x * af[k].x + af[k].y * af[k].y + af[k].z * af[k].z + af[k].w * af[k].w;
            sqp += pv.x * pv.x + pv.y * pv.y + pv.z * pv.z + pv.w * pv.w;
        }
#pragma unroll
        for (int o = 16; o; o >>= 1) {
            dot += __shfl_xor_sync(0xffffffffu, dot, o);
            sqa += __shfl_xor_sync(0xffffffffu, sqa, o);
            sqp += __shfl_xor_sync(0xffffffffu, sqp, o);
        }
        if (lane == 0) {
            const float na = sqrtf(sqa);
            const float sim = dot / fmaxf(na * sqrtf(sqp), EPS_F);
            s_pos[w] = sim;
            if (w == 0) s_rinv = 1.0f / na;
            if (chunk == 0) g_pos_sim[b * NPOS + w] = sim;
        }
    }
    __syncthreads();

    const float rinv_a = s_rinv;
    const float t0 = s_pos[0], t1 = s_pos[1], t2 = s_pos[2], t3 = s_pos[3];

    float sum_exp = 0.f;
    int c0 = 0, c1 = 0, c2 = 0, c3 = 0;

    // warp w owns rows [w*32, w*32+32) of this chunk
    const float4* neg_base = reinterpret_cast<const float4*>(
        negatives + ((size_t)b * NNEG + chunk * ROWS_PER_CHUNK + w * ROWS_PER_WARP) * DIM);
    // per-row stride in float4 units
    const int ROW4 = DIM / 4;   // 128

    // ---- software-pipelined streaming loop ----
    float4 v[RBATCH][4];
#pragma unroll
    for (int r = 0; r < RBATCH; r++)
#pragma unroll
        for (int k = 0; k < 4; k++)
            v[r][k] = ldcs4(neg_base + (size_t)r * ROW4 + lane + 32 * k);

    for (int i = 0; i < ROWS_PER_WARP; i += RBATCH) {
        // 1) consume v into per-lane partials (frees the v registers)
        float dot[RBATCH], sq[RBATCH];
#pragma unroll
        for (int r = 0; r < RBATCH; r++) {
            float d = 0.f, s = 0.f;
#pragma unroll
            for (int k = 0; k < 4; k++) {
                d += af[k].x * v[r][k].x + af[k].y * v[r][k].y +
                     af[k].z * v[r][k].z + af[k].w * v[r][k].w;
                s += v[r][k].x * v[r][k].x + v[r][k].y * v[r][k].y +
                     v[r][k].z * v[r][k].z + v[r][k].w * v[r][k].w;
            }
            dot[r] = d;
            sq[r]  = s;
        }

        // 2) issue next batch's loads NOW — in flight through the whole tail
        if (i + RBATCH < ROWS_PER_WARP) {
#pragma unroll
            for (int r = 0; r < RBATCH; r++)
#pragma unroll
                for (int k = 0; k < 4; k++)
                    v[r][k] = ldcs4(neg_base + (size_t)(i + RBATCH + r) * ROW4 + lane + 32 * k);
        }

        // 3) interleaved butterfly reductions (8 independent chains per level)
#pragma unroll
        for (int o = 16; o; o >>= 1) {
#pragma unroll
            for (int r = 0; r < RBATCH; r++) {
                dot[r] += __shfl_xor_sync(0xffffffffu, dot[r], o);
                sq[r]  += __shfl_xor_sync(0xffffffffu, sq[r], o);
            }
        }

        // 4) sim tail
#pragma unroll
        for (int r = 0; r < RBATCH; r++) {
            const float sim = dot[r] * (rinv_a * rsqrtf(fmaxf(sq[r], EPS_F * EPS_F)));
            sum_exp += __expf(sim * INV_T);
            c0 += (sim > t0);
            c1 += (sim > t1);
            c2 += (sim > t2);
            c3 += (sim > t3);
        }
    }

    // ---- block reduction of partials ----
    if (lane == 0) {
        s_exp[w]    = sum_exp;
        s_cnt[w][0] = c0; s_cnt[w][1] = c1; s_cnt[w][2] = c2; s_cnt[w][3] = c3;
    }
    __syncthreads();
    if (threadIdx.x == 0) {
        float se = 0.f;
        int k0 = 0, k1 = 0, k2 = 0, k3 = 0;
#pragma unroll
        for (int j = 0; j < WARPS_B; j++) {
            se += s_exp[j];
            k0 += s_cnt[j][0]; k1 += s_cnt[j][1]; k2 += s_cnt[j][2]; k3 += s_cnt[j][3];
        }
        g_exp_part[blockIdx.x] = se;
        g_cnt_part[blockIdx.x] = make_int4(k0, k1, k2, k3);
        __threadfence();                       // partials visible before ticket
        const unsigned int t = atomicAdd(&g_ticket, 1u);
        s_last = (t == NBLOCKS - 1u) ? 1 : 0;
    }
    __syncthreads();

    // ---- last block finalizes (deterministic fixed-order fold) ----
    if (s_last) {
        const int bb = threadIdx.x;            // thread = batch index

        float se = 0.f;
        int cnt[NPOS] = {0, 0, 0, 0};
#pragma unroll
        for (int c = 0; c < CHUNKS; c++) {
            const int idx = bb * CHUNKS + c;
            se += g_exp_part[idx];
            const int4 k = g_cnt_part[idx];
            cnt[0] += k.x; cnt[1] += k.y; cnt[2] += k.z; cnt[3] += k.w;
        }

        float ps[NPOS], ep[NPOS];
        float denom = se;
#pragma unroll
        for (int p = 0; p < NPOS; p++) {
            ps[p] = g_pos_sim[bb * NPOS + p];
            ep[p] = expf(ps[p] * INV_T);
            denom += ep[p];
        }

        float err = 0.f, psum = 0.f;
#pragma unroll
        for (int p = 0; p < NPOS; p++) {
            int rank = cnt[p];
#pragma unroll
            for (int q = 0; q < NPOS; q++) {
                if (ps[q] > ps[p]) rank++;
                else if (q < p && ps[q] == ps[p]) rank++;
            }
            err  += (ep[p] / denom) / (float)(rank + 1);
            psum += ps[p];
        }

        __shared__ float s_err[256];
        __shared__ float s_psum[256];
        s_err[bb]  = err;
        s_psum[bb] = psum;
        __syncthreads();
        for (int off = 128; off; off >>= 1) {
            if (bb < off) {
                s_err[bb]  += s_err[bb + off];
                s_psum[bb] += s_psum[bb + off];
            }
            __syncthreads();
        }
        if (bb == 0) {
            out[0] = -s_err[0] / (float)BATCH +
                     0.3f * (1.0f - s_psum[0] / (float)(BATCH * NPOS));
            g_ticket = 0;                      // re-arm for next (graph) replay
        }
    }
}

// ---------------------------------------------------------------------------
extern "C" void kernel_launch(void* const* d_in, const int* in_sizes, int n_in,
                              void* d_out, int out_size) {
    const float* anchor    = (const float*)d_in[0];
    const float* positives = (const float*)d_in[1];
    const float* negatives = (const float*)d_in[2];

    rrl_fused_kernel<<<NBLOCKS, 256>>>(anchor, positives, negatives, (float*)d_out);
}